// round 15
// baseline (speedup 1.0000x reference)
#include <cuda_runtime.h>
#include <math.h>
#include <stdint.h>

#define HIST     50
#define NUMD     32
#define NCAT     8
#define CATD     16
#define REGD     32
#define INDIM    242
#define HID      64
#define KEXP     64
#define TOPK     8
#define HASHB    32768
#define GEOB     4096
#define B_ROWS   524288

#define THREADS  512
#define TILE_M   64
#define NTILES   (B_ROWS / TILE_M)   // 8192
#define XS       132                  // floats per k-row: 64 rows DUPLICATED (128) + 4 pad
                                      // 132*4 = 528 B = 33*16 -> LDS.128-aligned rows
#define XS2      (XS / 2)             // float2 stride
#define LGS      68                   // logit scratch row stride (floats)

// ---- SMEM layout (byte offsets). H/H2/logits alias the X region. ----
#define OFF_X      0                 // 242*132*4 = 127776
#define OFF_H      0                 //  64*132*4 = 33792 (X dead after L1)
#define OFF_H2     34816             //  33792 (ends 68608)
#define OFF_LG     69632             //  64*68*4 = 17408 (ends 87040 < 127776)
#define OFF_W1     127872            // 61952
#define OFF_W2     189824            // 16384
#define OFF_W3     206208            // 16384
#define OFF_B1     222592
#define OFF_B2     222848
#define OFF_B3     223104
#define SMEM_TOTAL 223360

typedef unsigned long long u64;

// ---- packed f32x2 helpers (FFMA2: bit-identical fp32 math, 2 FMA/instr) ----
__device__ __forceinline__ void upk2(u64 p, float& lo, float& hi) {
    asm("mov.b64 {%0, %1}, %2;" : "=f"(lo), "=f"(hi) : "l"(p));
}
__device__ __forceinline__ void fma2(u64& d, u64 a, u64 b) {
    asm("fma.rn.f32x2 %0, %1, %2, %0;" : "+l"(d) : "l"(a), "l"(b));
}

__device__ __forceinline__ float gelu_exact(float x) {
    return 0.5f * x * (1.0f + erff(x * 0.70710678118654752440f));
}

// ---- GEMM on duplicated-A: thread = 2 rows x 4 cols, k ascending (bitwise) ----
// A: k-major duplicated [K][XS] where A[k][2r]=A[k][2r+1]=x[r][k].
// W: k-major [K][64].  acc[r][cp]: row r0+r, col pair (c0+2cp, c0+2cp+1).
// Inner loop: 2x LDS.128 + 4 FFMA2 — no dup-MOVs at all.
template<int K>
__device__ __forceinline__ void gemm_rt(const float* __restrict__ A,
                                        const float* __restrict__ W,
                                        int r0, int c0,
                                        u64 acc[2][2]) {
    acc[0][0] = 0ull; acc[0][1] = 0ull;
    acc[1][0] = 0ull; acc[1][1] = 0ull;

    const char* a = (const char*)(A + 2 * r0);   // 16B-aligned (r0 even)
    const char* w = (const char*)(W + c0);
    #pragma unroll 4
    for (int k = 0; k < K; ++k) {
        const ulonglong2 xq = *reinterpret_cast<const ulonglong2*>(a); // (x_r0 dup, x_r0+1 dup)
        const ulonglong2 wq = *reinterpret_cast<const ulonglong2*>(w); // 2 native col pairs
        fma2(acc[0][0], xq.x, wq.x);
        fma2(acc[0][1], xq.x, wq.y);
        fma2(acc[1][0], xq.y, wq.x);
        fma2(acc[1][1], xq.y, wq.y);
        a += XS * 4; w += 64 * 4;
    }
}

// gelu(acc + bias) -> duplicated k-major DST[c][2r..2r+3] (one float4 per col)
__device__ __forceinline__ void act_store(const u64 acc[2][2],
                                          float4 bv, float* __restrict__ DST,
                                          int r0, int c0) {
    float g[2][4];
    upk2(acc[0][0], g[0][0], g[0][1]);
    upk2(acc[0][1], g[0][2], g[0][3]);
    upk2(acc[1][0], g[1][0], g[1][1]);
    upk2(acc[1][1], g[1][2], g[1][3]);
    const float bb[4] = { bv.x, bv.y, bv.z, bv.w };
    #pragma unroll
    for (int r = 0; r < 2; ++r)
        #pragma unroll
        for (int c = 0; c < 4; ++c)
            g[r][c] = gelu_exact(g[r][c] + bb[c]);
    #pragma unroll
    for (int c = 0; c < 4; ++c)
        *reinterpret_cast<float4*>(DST + (c0 + c) * XS + 2 * r0) =
            make_float4(g[0][c], g[0][c], g[1][c], g[1][c]);
}

__global__ __launch_bounds__(THREADS, 1)
void gating_kernel(const float* __restrict__ hist,
                   const float* __restrict__ num,
                   const int*   __restrict__ cat,
                   const int*   __restrict__ region,
                   const float* __restrict__ catT,
                   const float* __restrict__ regT,
                   const float* __restrict__ W1, const float* __restrict__ b1,
                   const float* __restrict__ W2, const float* __restrict__ b2,
                   const float* __restrict__ W3, const float* __restrict__ b3,
                   float* __restrict__ out)
{
    extern __shared__ __align__(16) char sm[];
    const int tid  = threadIdx.x;
    const int wid  = tid >> 5;
    const int lane = tid & 31;

    float*  sx   = (float*)(sm + OFF_X);
    float2* sx2  = (float2*)(sm + OFF_X);
    float*  sh   = (float*)(sm + OFF_H);
    float*  sh2  = (float*)(sm + OFF_H2);
    float*  slg  = (float*)(sm + OFF_LG);
    float*  sw1  = (float*)(sm + OFF_W1);
    float*  sw2  = (float*)(sm + OFF_W2);
    float*  sw3  = (float*)(sm + OFF_W3);

    // ---- stage weights (k-major, direct copy) + biases ----
    for (int i = tid; i < INDIM * 64 / 4; i += THREADS)
        ((float4*)sw1)[i] = ((const float4*)W1)[i];
    for (int i = tid; i < 64 * 64 / 4; i += THREADS) {
        ((float4*)sw2)[i] = ((const float4*)W2)[i];
        ((float4*)sw3)[i] = ((const float4*)W3)[i];
    }
    if (tid < 64) {
        ((float*)(sm + OFF_B1))[tid] = b1[tid];
        ((float*)(sm + OFF_B2))[tid] = b2[tid];
        ((float*)(sm + OFF_B3))[tid] = b3[tid];
    }
    __syncthreads();

    // GEMM mapping: warp = 8 rows x 32 cols; thread = 2 rows x 4 cols
    const int warpRow = (wid & 7) * 8;          // 8 row-groups of 8
    const int warpCol = (wid >> 3) * 32;        // 2 col halves
    const int r0 = warpRow + (lane & 3) * 2;    // even -> 16B-aligned dup loads
    const int c0 = warpCol + (lane >> 2) * 4;

    const float4 b1v = *(const float4*)((const float*)(sm + OFF_B1) + c0);
    const float4 b2v = *(const float4*)((const float*)(sm + OFF_B2) + c0);
    const float4 b3v = *(const float4*)((const float*)(sm + OFF_B3) + c0);

    for (int tile = blockIdx.x; tile < NTILES; tile += gridDim.x) {
        const int rbase = tile * TILE_M;

        // ---- gather -> X duplicated: value stored as (v,v) float2; warp = 4 rows ----
        {
            const int wrow = wid * 4;
            #pragma unroll
            for (int rr = 0; rr < 4; ++rr) {
                const int lr = wrow + rr;
                const size_t row = (size_t)(rbase + lr);
                {
                    const float v = hist[row * HIST + lane];
                    sx2[lane * XS2 + lr] = make_float2(v, v);
                }
                if (lane < HIST - 32) {
                    const float v = hist[row * HIST + 32 + lane];
                    sx2[(32 + lane) * XS2 + lr] = make_float2(v, v);
                }
                {
                    const float v = num[row * NUMD + lane];
                    sx2[(HIST + lane) * XS2 + lr] = make_float2(v, v);
                }
                #pragma unroll
                for (int i = 0; i < 4; ++i) {
                    const int t = lane + 32 * i;
                    const int j = t >> 4, d = t & 15;
                    int idx = cat[row * NCAT + j];
                    idx = min(max(idx, 0), HASHB - 1);
                    const float v = catT[((size_t)(j * HASHB + idx)) * CATD + d];
                    sx2[(HIST + NUMD + t) * XS2 + lr] = make_float2(v, v);
                }
                {
                    int rid = region[row];
                    rid = min(max(rid, 0), GEOB - 1);
                    const float v = regT[(size_t)rid * REGD + lane];
                    sx2[(HIST + NUMD + NCAT * CATD + lane) * XS2 + lr] = make_float2(v, v);
                }
            }
        }
        __syncthreads();

        u64 acc[2][2];

        // ---- layer 1 (K=242) ----
        gemm_rt<INDIM>(sx, sw1, r0, c0, acc);
        __syncthreads();                       // all X reads done (H aliases X)
        act_store(acc, b1v, sh, r0, c0);
        __syncthreads();                       // H ready

        // ---- layer 2 (K=64) ----
        gemm_rt<HID>(sh, sw2, r0, c0, acc);
        act_store(acc, b2v, sh2, r0, c0);      // H2 disjoint from H reads
        __syncthreads();                       // H2 ready

        // ---- layer 3 (K=64): logits (+bias) -> scratch, row-major float4 ----
        gemm_rt<HID>(sh2, sw3, r0, c0, acc);
        {
            const float bb[4] = { b3v.x, b3v.y, b3v.z, b3v.w };
            float g[2][4];
            upk2(acc[0][0], g[0][0], g[0][1]);
            upk2(acc[0][1], g[0][2], g[0][3]);
            upk2(acc[1][0], g[1][0], g[1][1]);
            upk2(acc[1][1], g[1][2], g[1][3]);
            #pragma unroll
            for (int r = 0; r < 2; ++r)
                *reinterpret_cast<float4*>(slg + (r0 + r) * LGS + c0) =
                    make_float4(g[r][0] + bb[0], g[r][1] + bb[1],
                                g[r][2] + bb[2], g[r][3] + bb[3]);
        }
        __syncthreads();   // slg ready

        // ---- overlapped epilogue (R8 pattern, 64 rows) ----
        // threads 64-511: zero the output tile in gmem (64 x 64 f32 = 1024 float4)
        // threads 0-63 : per-row top-8 + softmax (results held in registers)
        float sv[TOPK]; int si[TOPK];
        if (tid >= 64) {
            float4* obase = reinterpret_cast<float4*>(out + (size_t)rbase * KEXP);
            const float4 z = make_float4(0.f, 0.f, 0.f, 0.f);
            const int t = tid - 64;             // 0..447
            obase[t] = z;
            obase[t + 448] = z;                 // 448..895
            if (t < 128) obase[t + 896] = z;    // 896..1023
        } else {
            float v[KEXP];
            #pragma unroll
            for (int g = 0; g < 16; ++g) {
                const float4 t4 = *reinterpret_cast<const float4*>(slg + tid * LGS + g * 4);
                v[4 * g] = t4.x; v[4 * g + 1] = t4.y; v[4 * g + 2] = t4.z; v[4 * g + 3] = t4.w;
            }
            unsigned long long used = 0ull;
            #pragma unroll
            for (int it = 0; it < TOPK; ++it) {
                float bv = -INFINITY; int bi = 0;
                #pragma unroll
                for (int i = 0; i < KEXP; ++i) {
                    const bool take = (((used >> i) & 1ull) == 0ull) && (v[i] > bv);
                    if (take) { bv = v[i]; bi = i; }   // strict > : lowest index on ties
                }
                used |= 1ull << bi; sv[it] = bv; si[it] = bi;
            }
            const float vmax = sv[0];
            float ssum = 0.f;
            #pragma unroll
            for (int t = 0; t < TOPK; ++t) { sv[t] = expf(sv[t] - vmax); ssum += sv[t]; }
            const float inv = 1.0f / ssum;
            #pragma unroll
            for (int t = 0; t < TOPK; ++t) sv[t] *= inv;
        }
        __syncthreads();   // zeros ordered before scatters (same CTA)

        if (tid < 64) {
            float* orow = out + (size_t)(rbase + tid) * KEXP;
            #pragma unroll
            for (int t = 0; t < TOPK; ++t) orow[si[t]] = sv[t];
        }
        __syncthreads();   // slg / X region free for next tile's gather
    }
}

extern "C" void kernel_launch(void* const* d_in, const int* in_sizes, int n_in,
                              void* d_out, int out_size)
{
    const float* hist   = (const float*)d_in[0];
    const float* num    = (const float*)d_in[1];
    const int*   cat    = (const int*)  d_in[2];
    const int*   region = (const int*)  d_in[3];
    const float* catT   = (const float*)d_in[4];
    const float* regT   = (const float*)d_in[5];
    const float* W1     = (const float*)d_in[6];
    const float* b1     = (const float*)d_in[7];
    const float* W2     = (const float*)d_in[8];
    const float* b2     = (const float*)d_in[9];
    const float* W3     = (const float*)d_in[10];
    const float* b3     = (const float*)d_in[11];
    float* out = (float*)d_out;

    cudaFuncSetAttribute(gating_kernel,
                         cudaFuncAttributeMaxDynamicSharedMemorySize, SMEM_TOTAL);
    gating_kernel<<<148, THREADS, SMEM_TOTAL>>>(
        hist, num, cat, region, catT, regT, W1, b1, W2, b2, W3, b3, out);
}

// round 16
// speedup vs baseline: 1.4580x; 1.4580x over previous
#include <cuda_runtime.h>
#include <math.h>
#include <stdint.h>

#define HIST     50
#define NUMD     32
#define NCAT     8
#define CATD     16
#define REGD     32
#define INDIM    242
#define HID      64
#define KEXP     64
#define TOPK     8
#define HASHB    32768
#define GEOB     4096
#define B_ROWS   524288

#define THREADS  512
#define TILE_M   128
#define NTILES   (B_ROWS / TILE_M)   // 4096
#define XS       132                  // floats per k-row (16B-aligned stride)
#define LGS      68                   // logit scratch row stride (floats)
#define CSTR     34                   // cand row stride (float2 units)

// ---- SMEM layout (byte offsets). H/H2/logits/cand alias the X region. ----
#define OFF_X      0                 // 242*132*4 = 127776
#define OFF_H      0                 //  64*132*4 = 33792 (X dead after L1)
#define OFF_CAND   0                 // 128*34*8 = 34816 (H dead after L2)
#define OFF_H2     34816             //  33792 (ends 68608)
#define OFF_LG     69632             // 128*68*4 = 34816 (ends 104448 < 127776)
#define OFF_W1     127872            // 61952
#define OFF_W2     189824            // 16384
#define OFF_W3     206208            // 16384
#define OFF_B1     222592
#define OFF_B2     222848
#define OFF_B3     223104
#define SMEM_TOTAL 223360

typedef unsigned long long u64;

// ---- packed f32x2 helpers (FFMA2: bit-identical fp32 math, 2 FMA/instr) ----
__device__ __forceinline__ u64 pk2(float lo, float hi) {
    u64 r;
    asm("mov.b64 %0, {%1, %2};" : "=l"(r) : "f"(lo), "f"(hi));
    return r;
}
__device__ __forceinline__ void upk2(u64 p, float& lo, float& hi) {
    asm("mov.b64 {%0, %1}, %2;" : "=f"(lo), "=f"(hi) : "l"(p));
}
__device__ __forceinline__ void fma2(u64& d, u64 a, u64 b) {
    asm("fma.rn.f32x2 %0, %1, %2, %0;" : "+l"(d) : "l"(a), "l"(b));
}

__device__ __forceinline__ float gelu_exact(float x) {
    return 0.5f * x * (1.0f + erff(x * 0.70710678118654752440f));
}

// ---- register-tiled GEMM (R8 core, FROZEN): thread = 4 rows x 4 cols ----
// A: k-major [K][XS]; W: k-major [K][64]. k ascending (bitwise fp32).
template<int K>
__device__ __forceinline__ void gemm_rt(const float* __restrict__ A,
                                        const float* __restrict__ W,
                                        int r0, int c0,
                                        u64 acc[4][2]) {
    #pragma unroll
    for (int r = 0; r < 4; ++r) { acc[r][0] = 0ull; acc[r][1] = 0ull; }

    const float* a = A + r0;
    const float* w = W + c0;
    #pragma unroll 4
    for (int k = 0; k < K; ++k) {
        const float4 xv = *reinterpret_cast<const float4*>(a);
        const ulonglong2 wq = *reinterpret_cast<const ulonglong2*>(w);
        const u64 xd[4] = { pk2(xv.x, xv.x), pk2(xv.y, xv.y),
                            pk2(xv.z, xv.z), pk2(xv.w, xv.w) };
        #pragma unroll
        for (int r = 0; r < 4; ++r) {
            fma2(acc[r][0], xd[r], wq.x);
            fma2(acc[r][1], xd[r], wq.y);
        }
        a += XS; w += 64;
    }
}

// gelu(acc + bias) -> k-major DST[c][r] for the next layer
__device__ __forceinline__ void act_store(const u64 acc[4][2],
                                          float4 bv, float* __restrict__ DST,
                                          int r0, int c0) {
    float gv[4][4];
    #pragma unroll
    for (int r = 0; r < 4; ++r) {
        upk2(acc[r][0], gv[r][0], gv[r][1]);
        upk2(acc[r][1], gv[r][2], gv[r][3]);
    }
    const float bb[4] = { bv.x, bv.y, bv.z, bv.w };
    #pragma unroll
    for (int r = 0; r < 4; ++r)
        #pragma unroll
        for (int c = 0; c < 4; ++c)
            gv[r][c] = gelu_exact(gv[r][c] + bb[c]);
    #pragma unroll
    for (int c = 0; c < 4; ++c)
        *reinterpret_cast<float4*>(DST + (c0 + c) * XS + r0) =
            make_float4(gv[0][c], gv[1][c], gv[2][c], gv[3][c]);
}

__global__ __launch_bounds__(THREADS, 1)
void gating_kernel(const float* __restrict__ hist,
                   const float* __restrict__ num,
                   const int*   __restrict__ cat,
                   const int*   __restrict__ region,
                   const float* __restrict__ catT,
                   const float* __restrict__ regT,
                   const float* __restrict__ W1, const float* __restrict__ b1,
                   const float* __restrict__ W2, const float* __restrict__ b2,
                   const float* __restrict__ W3, const float* __restrict__ b3,
                   float* __restrict__ out)
{
    extern __shared__ __align__(16) char sm[];
    const int tid  = threadIdx.x;
    const int wid  = tid >> 5;
    const int lane = tid & 31;

    float*  sx   = (float*)(sm + OFF_X);
    float*  sh   = (float*)(sm + OFF_H);
    float*  sh2  = (float*)(sm + OFF_H2);
    float*  slg  = (float*)(sm + OFF_LG);
    float2* cand = (float2*)(sm + OFF_CAND);
    float*  sw1  = (float*)(sm + OFF_W1);
    float*  sw2  = (float*)(sm + OFF_W2);
    float*  sw3  = (float*)(sm + OFF_W3);

    // ---- stage weights (k-major, direct copy) + biases ----
    for (int i = tid; i < INDIM * 64 / 4; i += THREADS)
        ((float4*)sw1)[i] = ((const float4*)W1)[i];
    for (int i = tid; i < 64 * 64 / 4; i += THREADS) {
        ((float4*)sw2)[i] = ((const float4*)W2)[i];
        ((float4*)sw3)[i] = ((const float4*)W3)[i];
    }
    if (tid < 64) {
        ((float*)(sm + OFF_B1))[tid] = b1[tid];
        ((float*)(sm + OFF_B2))[tid] = b2[tid];
        ((float*)(sm + OFF_B3))[tid] = b3[tid];
    }
    __syncthreads();

    // GEMM mapping (R8): warp = 16 rows x 32 cols; thread = 4 rows x 4 cols
    const int warpRow = (wid & 7) * 16;
    const int warpCol = (wid >> 3) * 32;
    const int r0 = warpRow + (lane & 3) * 4;
    const int c0 = warpCol + (lane >> 2) * 4;

    const float4 b1v = *(const float4*)((const float*)(sm + OFF_B1) + c0);
    const float4 b2v = *(const float4*)((const float*)(sm + OFF_B2) + c0);
    const float4 b3v = *(const float4*)((const float*)(sm + OFF_B3) + c0);

    // gather lane roles for cat: cj = embedding slot, ce = float4 quarter
    const int cj = lane >> 2;          // 0..7
    const int ce = lane & 3;           // 0..3

    for (int tile = blockIdx.x; tile < NTILES; tile += gridDim.x) {
        const int rbase = tile * TILE_M;

        // ---- hoisted zeroing of this tile's output (drains under gather/GEMM) ----
        {
            float4* obase = reinterpret_cast<float4*>(out + (size_t)rbase * KEXP);
            const float4 z = make_float4(0.f, 0.f, 0.f, 0.f);
            #pragma unroll
            for (int j = 0; j < 4; ++j) obase[tid + j * THREADS] = z;
        }

        // ---- gather -> X[k][r] (k-major); warp = 8 rows, lanes spread k ----
        {
            const int wrow = wid * 8;
            #pragma unroll 2
            for (int rr = 0; rr < 8; ++rr) {
                const int lr = wrow + rr;
                const size_t row = (size_t)(rbase + lr);
                sx[lane * XS + lr] = hist[row * HIST + lane];
                if (lane < HIST - 32)
                    sx[(32 + lane) * XS + lr] = hist[row * HIST + 32 + lane];
                sx[(HIST + lane) * XS + lr] = num[row * NUMD + lane];
                // cat: one idx LDG + one float4 LDG per lane (quarter-warp coalesced)
                {
                    int idx = cat[row * NCAT + cj];
                    idx = min(max(idx, 0), HASHB - 1);
                    const float4 cv = *reinterpret_cast<const float4*>(
                        catT + ((size_t)(cj * HASHB + idx)) * CATD + 4 * ce);
                    const int kb = HIST + NUMD + cj * CATD + 4 * ce;
                    sx[(kb + 0) * XS + lr] = cv.x;
                    sx[(kb + 1) * XS + lr] = cv.y;
                    sx[(kb + 2) * XS + lr] = cv.z;
                    sx[(kb + 3) * XS + lr] = cv.w;
                }
                int rid = region[row];
                rid = min(max(rid, 0), GEOB - 1);
                sx[(HIST + NUMD + NCAT * CATD + lane) * XS + lr] = regT[(size_t)rid * REGD + lane];
            }
        }
        __syncthreads();

        u64 acc[4][2];

        // ---- layer 1 (K=242) ----
        gemm_rt<INDIM>(sx, sw1, r0, c0, acc);
        __syncthreads();                       // all X reads done (H aliases X)
        act_store(acc, b1v, sh, r0, c0);
        __syncthreads();                       // H ready

        // ---- layer 2 (K=64) ----
        gemm_rt<HID>(sh, sw2, r0, c0, acc);
        act_store(acc, b2v, sh2, r0, c0);      // H2 disjoint from H reads
        __syncthreads();                       // H2 ready

        // ---- layer 3 (K=64): logits (+bias) -> scratch, row-major float4 ----
        gemm_rt<HID>(sh2, sw3, r0, c0, acc);
        {
            const float bb[4] = { b3v.x, b3v.y, b3v.z, b3v.w };
            #pragma unroll
            for (int r = 0; r < 4; ++r) {
                float l0, l1, l2, l3;
                upk2(acc[r][0], l0, l1);
                upk2(acc[r][1], l2, l3);
                *reinterpret_cast<float4*>(slg + (r0 + r) * LGS + c0) =
                    make_float4(l0 + bb[0], l1 + bb[1], l2 + bb[2], l3 + bb[3]);
            }
        }
        __syncthreads();   // slg ready; also orders the hoisted zero-stores

        // ---- epilogue phase 1: all 512 threads, 4 per row, local top-8 of 16 ----
        // produces 4 descending candidate lists per row (ties -> lowest col first)
        {
            const int prow = tid >> 2;      // 0..127
            const int pq   = tid & 3;       // column block of 16
            float v[16];
            #pragma unroll
            for (int g = 0; g < 4; ++g) {
                const float4 t4 = *reinterpret_cast<const float4*>(
                    slg + prow * LGS + pq * 16 + 4 * g);
                v[4 * g] = t4.x; v[4 * g + 1] = t4.y;
                v[4 * g + 2] = t4.z; v[4 * g + 3] = t4.w;
            }
            unsigned used = 0u;
            #pragma unroll
            for (int it = 0; it < TOPK; ++it) {
                float bv = -INFINITY; int bi = 0;
                #pragma unroll
                for (int i = 0; i < 16; ++i) {
                    const bool take = (((used >> i) & 1u) == 0u) && (v[i] > bv);
                    if (take) { bv = v[i]; bi = i; }   // strict > : lowest col on ties
                }
                used |= 1u << bi;
                cand[prow * CSTR + pq * 8 + it] =
                    make_float2(bv, __int_as_float(pq * 16 + bi));
            }
        }
        __syncthreads();

        // ---- epilogue phase 2: threads 0-127, 4-way sorted merge, softmax, scatter ----
        if (tid < TILE_M) {
            const float2* crow = cand + tid * CSTR;
            float hv[4]; int hix[4]; int hp[4];
            #pragma unroll
            for (int l = 0; l < 4; ++l) {
                const float2 h = crow[l * 8];
                hv[l] = h.x; hix[l] = __float_as_int(h.y); hp[l] = 1;
            }
            float sv[TOPK]; int si[TOPK];
            #pragma unroll
            for (int it = 0; it < TOPK; ++it) {
                int bl = 0;
                #pragma unroll
                for (int l = 1; l < 4; ++l) {
                    const bool better = (hv[l] > hv[bl]) ||
                                        (hv[l] == hv[bl] && hix[l] < hix[bl]);
                    if (better) bl = l;
                }
                sv[it] = hv[bl]; si[it] = hix[bl];
                if (hp[bl] < 8) {
                    const float2 h = crow[bl * 8 + hp[bl]];
                    hv[bl] = h.x; hix[bl] = __float_as_int(h.y);
                } else {
                    hv[bl] = -INFINITY; hix[bl] = 1 << 30;
                }
                ++hp[bl];
            }
            const float vmax = sv[0];
            float ssum = 0.f;
            #pragma unroll
            for (int t = 0; t < TOPK; ++t) { sv[t] = expf(sv[t] - vmax); ssum += sv[t]; }
            const float inv = 1.0f / ssum;
            float* orow = out + (size_t)(rbase + tid) * KEXP;
            #pragma unroll
            for (int t = 0; t < TOPK; ++t) orow[si[t]] = sv[t] * inv;
        }
        __syncthreads();   // cand/X region free for next tile's gather
    }
}

extern "C" void kernel_launch(void* const* d_in, const int* in_sizes, int n_in,
                              void* d_out, int out_size)
{
    const float* hist   = (const float*)d_in[0];
    const float* num    = (const float*)d_in[1];
    const int*   cat    = (const int*)  d_in[2];
    const int*   region = (const int*)  d_in[3];
    const float* catT   = (const float*)d_in[4];
    const float* regT   = (const float*)d_in[5];
    const float* W1     = (const float*)d_in[6];
    const float* b1     = (const float*)d_in[7];
    const float* W2     = (const float*)d_in[8];
    const float* b2     = (const float*)d_in[9];
    const float* W3     = (const float*)d_in[10];
    const float* b3     = (const float*)d_in[11];
    float* out = (float*)d_out;

    cudaFuncSetAttribute(gating_kernel,
                         cudaFuncAttributeMaxDynamicSharedMemorySize, SMEM_TOTAL);
    gating_kernel<<<148, THREADS, SMEM_TOTAL>>>(
        hist, num, cat, region, catT, regT, W1, b1, W2, b2, W3, b3, out);
}

// round 17
// speedup vs baseline: 1.5422x; 1.0578x over previous
#include <cuda_runtime.h>
#include <math.h>
#include <stdint.h>

#define HIST     50
#define NUMD     32
#define NCAT     8
#define CATD     16
#define REGD     32
#define INDIM    242
#define HID      64
#define KEXP     64
#define TOPK     8
#define HASHB    32768
#define GEOB     4096
#define B_ROWS   524288

#define THREADS  512
#define TILE_M   128
#define NTILES   (B_ROWS / TILE_M)   // 4096
#define XS       132                  // floats per k-row (16B-aligned stride)
#define LGS      68                   // logit scratch row stride (floats)
#define CSTR     34                   // cand row stride (float2 units)

// ---- SMEM layout (byte offsets). H/H2/logits/cand alias the X region. ----
#define OFF_X      0                 // 242*132*4 = 127776
#define OFF_H      0                 //  64*132*4 = 33792 (X dead after L1)
#define OFF_CAND   0                 // 128*34*8 = 34816 (H dead after L2)
#define OFF_H2     34816             //  33792 (ends 68608)
#define OFF_LG     69632             // 128*68*4 = 34816 (ends 104448 < 127776)
#define OFF_W1     127872            // 61952
#define OFF_W2     189824            // 16384
#define OFF_W3     206208            // 16384
#define OFF_B1     222592
#define OFF_B2     222848
#define OFF_B3     223104
#define SMEM_TOTAL 223360

typedef unsigned long long u64;

// ---- packed f32x2 helpers (FFMA2: bit-identical fp32 math, 2 FMA/instr) ----
__device__ __forceinline__ u64 pk2(float lo, float hi) {
    u64 r;
    asm("mov.b64 %0, {%1, %2};" : "=l"(r) : "f"(lo), "f"(hi));
    return r;
}
__device__ __forceinline__ void upk2(u64 p, float& lo, float& hi) {
    asm("mov.b64 {%0, %1}, %2;" : "=f"(lo), "=f"(hi) : "l"(p));
}
__device__ __forceinline__ void fma2(u64& d, u64 a, u64 b) {
    asm("fma.rn.f32x2 %0, %1, %2, %0;" : "+l"(d) : "l"(a), "l"(b));
}

__device__ __forceinline__ float gelu_exact(float x) {
    return 0.5f * x * (1.0f + erff(x * 0.70710678118654752440f));
}

// ---- register-tiled GEMM (R8 core, FROZEN): thread = 4 rows x 4 cols ----
// A: k-major [K][XS]; W: k-major [K][64]. k ascending (bitwise fp32).
template<int K>
__device__ __forceinline__ void gemm_rt(const float* __restrict__ A,
                                        const float* __restrict__ W,
                                        int r0, int c0,
                                        u64 acc[4][2]) {
    #pragma unroll
    for (int r = 0; r < 4; ++r) { acc[r][0] = 0ull; acc[r][1] = 0ull; }

    const float* a = A + r0;
    const float* w = W + c0;
    #pragma unroll 4
    for (int k = 0; k < K; ++k) {
        const float4 xv = *reinterpret_cast<const float4*>(a);
        const ulonglong2 wq = *reinterpret_cast<const ulonglong2*>(w);
        const u64 xd[4] = { pk2(xv.x, xv.x), pk2(xv.y, xv.y),
                            pk2(xv.z, xv.z), pk2(xv.w, xv.w) };
        #pragma unroll
        for (int r = 0; r < 4; ++r) {
            fma2(acc[r][0], xd[r], wq.x);
            fma2(acc[r][1], xd[r], wq.y);
        }
        a += XS; w += 64;
    }
}

// gelu(acc + bias) -> k-major DST[c][r] for the next layer
__device__ __forceinline__ void act_store(const u64 acc[4][2],
                                          float4 bv, float* __restrict__ DST,
                                          int r0, int c0) {
    float gv[4][4];
    #pragma unroll
    for (int r = 0; r < 4; ++r) {
        upk2(acc[r][0], gv[r][0], gv[r][1]);
        upk2(acc[r][1], gv[r][2], gv[r][3]);
    }
    const float bb[4] = { bv.x, bv.y, bv.z, bv.w };
    #pragma unroll
    for (int r = 0; r < 4; ++r)
        #pragma unroll
        for (int c = 0; c < 4; ++c)
            gv[r][c] = gelu_exact(gv[r][c] + bb[c]);
    #pragma unroll
    for (int c = 0; c < 4; ++c)
        *reinterpret_cast<float4*>(DST + (c0 + c) * XS + r0) =
            make_float4(gv[0][c], gv[1][c], gv[2][c], gv[3][c]);
}

__global__ __launch_bounds__(THREADS, 1)
void gating_kernel(const float* __restrict__ hist,
                   const float* __restrict__ num,
                   const int*   __restrict__ cat,
                   const int*   __restrict__ region,
                   const float* __restrict__ catT,
                   const float* __restrict__ regT,
                   const float* __restrict__ W1, const float* __restrict__ b1,
                   const float* __restrict__ W2, const float* __restrict__ b2,
                   const float* __restrict__ W3, const float* __restrict__ b3,
                   float* __restrict__ out)
{
    extern __shared__ __align__(16) char sm[];
    const int tid  = threadIdx.x;
    const int wid  = tid >> 5;
    const int lane = tid & 31;

    float*  sx   = (float*)(sm + OFF_X);
    float*  sh   = (float*)(sm + OFF_H);
    float*  sh2  = (float*)(sm + OFF_H2);
    float*  slg  = (float*)(sm + OFF_LG);
    float2* cand = (float2*)(sm + OFF_CAND);
    float*  sw1  = (float*)(sm + OFF_W1);
    float*  sw2  = (float*)(sm + OFF_W2);
    float*  sw3  = (float*)(sm + OFF_W3);

    // ---- stage weights (k-major, direct copy) + biases ----
    for (int i = tid; i < INDIM * 64 / 4; i += THREADS)
        ((float4*)sw1)[i] = ((const float4*)W1)[i];
    for (int i = tid; i < 64 * 64 / 4; i += THREADS) {
        ((float4*)sw2)[i] = ((const float4*)W2)[i];
        ((float4*)sw3)[i] = ((const float4*)W3)[i];
    }
    if (tid < 64) {
        ((float*)(sm + OFF_B1))[tid] = b1[tid];
        ((float*)(sm + OFF_B2))[tid] = b2[tid];
        ((float*)(sm + OFF_B3))[tid] = b3[tid];
    }
    __syncthreads();

    // GEMM mapping (R8): warp = 16 rows x 32 cols; thread = 4 rows x 4 cols
    const int warpRow = (wid & 7) * 16;
    const int warpCol = (wid >> 3) * 32;
    const int r0 = warpRow + (lane & 3) * 4;
    const int c0 = warpCol + (lane >> 2) * 4;

    const float4 b1v = *(const float4*)((const float*)(sm + OFF_B1) + c0);
    const float4 b2v = *(const float4*)((const float*)(sm + OFF_B2) + c0);
    const float4 b3v = *(const float4*)((const float*)(sm + OFF_B3) + c0);

    for (int tile = blockIdx.x; tile < NTILES; tile += gridDim.x) {
        const int rbase = tile * TILE_M;

        // ---- gather -> X[k][r] (k-major); warp = 8 rows, lanes spread k ----
        // (R8-exact: scalar cat loads, no stores ahead of these LDGs)
        {
            const int wrow = wid * 8;
            #pragma unroll 2
            for (int rr = 0; rr < 8; ++rr) {
                const int lr = wrow + rr;
                const size_t row = (size_t)(rbase + lr);
                sx[lane * XS + lr] = hist[row * HIST + lane];
                if (lane < HIST - 32)
                    sx[(32 + lane) * XS + lr] = hist[row * HIST + 32 + lane];
                sx[(HIST + lane) * XS + lr] = num[row * NUMD + lane];
                #pragma unroll
                for (int i = 0; i < 4; ++i) {
                    const int t = lane + 32 * i;
                    const int j = t >> 4, d = t & 15;
                    int idx = cat[row * NCAT + j];
                    idx = min(max(idx, 0), HASHB - 1);
                    sx[(HIST + NUMD + t) * XS + lr] = catT[(size_t)(j * HASHB + idx) * CATD + d];
                }
                int rid = region[row];
                rid = min(max(rid, 0), GEOB - 1);
                sx[(HIST + NUMD + NCAT * CATD + lane) * XS + lr] = regT[(size_t)rid * REGD + lane];
            }
        }
        __syncthreads();

        u64 acc[4][2];

        // ---- layer 1 (K=242) ----
        gemm_rt<INDIM>(sx, sw1, r0, c0, acc);
        __syncthreads();                       // all X reads done (H aliases X)
        act_store(acc, b1v, sh, r0, c0);
        __syncthreads();                       // H ready

        // ---- layer 2 (K=64) ----
        gemm_rt<HID>(sh, sw2, r0, c0, acc);
        act_store(acc, b2v, sh2, r0, c0);      // H2 disjoint from H reads
        __syncthreads();                       // H2 ready

        // ---- layer 3 (K=64): logits (+bias) -> scratch, row-major float4 ----
        gemm_rt<HID>(sh2, sw3, r0, c0, acc);
        {
            const float bb[4] = { b3v.x, b3v.y, b3v.z, b3v.w };
            #pragma unroll
            for (int r = 0; r < 4; ++r) {
                float l0, l1, l2, l3;
                upk2(acc[r][0], l0, l1);
                upk2(acc[r][1], l2, l3);
                *reinterpret_cast<float4*>(slg + (r0 + r) * LGS + c0) =
                    make_float4(l0 + bb[0], l1 + bb[1], l2 + bb[2], l3 + bb[3]);
            }
        }
        __syncthreads();   // slg ready

        // ---- epilogue phase 1: all 512 threads, 4 per row, local top-8 of 16 ----
        // produces 4 descending candidate lists per row (ties -> lowest col first)
        {
            const int prow = tid >> 2;      // 0..127
            const int pq   = tid & 3;       // column block of 16
            float v[16];
            #pragma unroll
            for (int g = 0; g < 4; ++g) {
                const float4 t4 = *reinterpret_cast<const float4*>(
                    slg + prow * LGS + pq * 16 + 4 * g);
                v[4 * g] = t4.x; v[4 * g + 1] = t4.y;
                v[4 * g + 2] = t4.z; v[4 * g + 3] = t4.w;
            }
            unsigned used = 0u;
            #pragma unroll
            for (int it = 0; it < TOPK; ++it) {
                float bv = -INFINITY; int bi = 0;
                #pragma unroll
                for (int i = 0; i < 16; ++i) {
                    const bool take = (((used >> i) & 1u) == 0u) && (v[i] > bv);
                    if (take) { bv = v[i]; bi = i; }   // strict > : lowest col on ties
                }
                used |= 1u << bi;
                cand[prow * CSTR + pq * 8 + it] =
                    make_float2(bv, __int_as_float(pq * 16 + bi));
            }
        }
        __syncthreads();

        // ---- epilogue phase 2: threads 0-127 merge+softmax; 128-511 zero output ----
        float sv[TOPK]; int si[TOPK];
        if (tid >= 128) {
            // zeroing overlapped with merge compute (R8's proven overlap slot)
            float4* obase = reinterpret_cast<float4*>(out + (size_t)rbase * KEXP);
            const float4 z = make_float4(0.f, 0.f, 0.f, 0.f);
            const int t = tid - 128;            // 0..383
            #pragma unroll
            for (int j = 0; j < 6; ++j) {
                const int idx = t + j * 384;    // 0..2047
                if (idx < 2048) obase[idx] = z;
            }
        } else {
            const float2* crow = cand + tid * CSTR;
            float hv[4]; int hix[4]; int hp[4];
            #pragma unroll
            for (int l = 0; l < 4; ++l) {
                const float2 h = crow[l * 8];
                hv[l] = h.x; hix[l] = __float_as_int(h.y); hp[l] = 1;
            }
            #pragma unroll
            for (int it = 0; it < TOPK; ++it) {
                int bl = 0;
                #pragma unroll
                for (int l = 1; l < 4; ++l) {
                    const bool better = (hv[l] > hv[bl]) ||
                                        (hv[l] == hv[bl] && hix[l] < hix[bl]);
                    if (better) bl = l;
                }
                sv[it] = hv[bl]; si[it] = hix[bl];
                if (hp[bl] < 8) {
                    const float2 h = crow[bl * 8 + hp[bl]];
                    hv[bl] = h.x; hix[bl] = __float_as_int(h.y);
                } else {
                    hv[bl] = -INFINITY; hix[bl] = 1 << 30;
                }
                ++hp[bl];
            }
            const float vmax = sv[0];
            float ssum = 0.f;
            #pragma unroll
            for (int t = 0; t < TOPK; ++t) { sv[t] = expf(sv[t] - vmax); ssum += sv[t]; }
            const float inv = 1.0f / ssum;
            #pragma unroll
            for (int t = 0; t < TOPK; ++t) sv[t] *= inv;
        }
        __syncthreads();   // zeros globally ordered before scatters (same CTA)

        if (tid < TILE_M) {
            float* orow = out + (size_t)(rbase + tid) * KEXP;
            #pragma unroll
            for (int t = 0; t < TOPK; ++t) orow[si[t]] = sv[t];
        }
        __syncthreads();   // cand/X region free for next tile's gather
    }
}

extern "C" void kernel_launch(void* const* d_in, const int* in_sizes, int n_in,
                              void* d_out, int out_size)
{
    const float* hist   = (const float*)d_in[0];
    const float* num    = (const float*)d_in[1];
    const int*   cat    = (const int*)  d_in[2];
    const int*   region = (const int*)  d_in[3];
    const float* catT   = (const float*)d_in[4];
    const float* regT   = (const float*)d_in[5];
    const float* W1     = (const float*)d_in[6];
    const float* b1     = (const float*)d_in[7];
    const float* W2     = (const float*)d_in[8];
    const float* b2     = (const float*)d_in[9];
    const float* W3     = (const float*)d_in[10];
    const float* b3     = (const float*)d_in[11];
    float* out = (float*)d_out;

    cudaFuncSetAttribute(gating_kernel,
                         cudaFuncAttributeMaxDynamicSharedMemorySize, SMEM_TOTAL);
    gating_kernel<<<148, THREADS, SMEM_TOTAL>>>(
        hist, num, cat, region, catT, regT, W1, b1, W2, b2, W3, b3, out);
}